// round 2
// baseline (speedup 1.0000x reference)
#include <cuda_runtime.h>
#include <cuda_fp16.h>
#include <cstdint>

// Routed capsule layer, B200.
// Shapes: x[64,1152,8], W[64,1152,16,8] -> out v[64,64,16]
// u[b,o,i,k] = sum_j W[o,i,k,j] x[b,i,j], 3 routing iterations.
// Trick: b_t = (sum_{tau<=t} v_tau) . u  (logits linear in history),
// iteration-1 coupling coefficients are exactly 1/64.
// u cached in fp16 (values ~N(0,0.14): no overflow, 8x less rounding than bf16).

#define NB 64
#define NI 1152
#define KI 8
#define NO 64
#define KO 16

#define K1_OC 8
#define K1_IC 16
#define NCH1 (NI / K1_IC)   // 72 i-chunks for k_u partials
#define K2_IC 64
#define NCH2 (NI / K2_IC)   // 18 i-chunks for k_route partials

// Scratch (static device arrays: no allocation in kernel_launch).
__device__ __half g_u[(size_t)NB * NI * NO * KO];               // 151 MB, layout [b][i][o][k]
__device__ float g_sp[(size_t)NCH1 * NB * NO * KO];             // 18.9 MB partial s buffers
__device__ float g_v1[NB * NO * KO];
__device__ float g_vsum[NB * NO * KO];

// ---------------------------------------------------------------------------
// K1: compute u (fp16, layout [b][i][o][k]) and per-i-chunk partial sums of u
// (for the uniform-c first iteration). Each thread owns one (o,k) and keeps
// its 8x8 W slice in registers across the whole batch loop -> W is read from
// DRAM exactly once.
// grid = (72 i-chunks, 8 o-chunks), 256 threads.
// ---------------------------------------------------------------------------
__global__ void __launch_bounds__(256, 2) k_u(const float* __restrict__ x,
                                              const float* __restrict__ W) {
    __shared__ float sX[K1_IC * KI];   // x tile for current b: 16 i x 8 j
    __shared__ float sS[256];          // per-thread partial-sum exchange

    const int ich = blockIdx.x;
    const int och = blockIdx.y;
    const int t = threadIdx.x;
    const int ih = t >> 7;           // which half of the 16 i's (0/1)
    const int o  = (t >> 4) & 7;     // local o
    const int k  = t & 15;
    const int og = och * K1_OC + o;  // global o

    // Register-resident W: W[og][ich*16 + ih*8 + i][k][0..7], i = 0..7
    float4 wr[16];
    {
        const float4* wp = (const float4*)(
            W + ((size_t)((og * NI) + ich * K1_IC + ih * 8) * KO + k) * KI);
        // stride between consecutive i = KO*KI floats = 32 float4
#pragma unroll
        for (int i = 0; i < 8; i++) {
            wr[2 * i]     = wp[i * 32];
            wr[2 * i + 1] = wp[i * 32 + 1];
        }
    }

    for (int b = 0; b < NB; b++) {
        __syncthreads();   // protect sX / sS from previous iteration readers
        if (t < 32) {
            ((float4*)sX)[t] =
                ((const float4*)(x + ((size_t)b * NI + ich * K1_IC) * KI))[t];
        }
        __syncthreads();

        float acc = 0.f;
        __half* up = g_u
            + ((size_t)(b * NI + ich * K1_IC + ih * 8)) * (NO * KO)
            + og * KO + k;
#pragma unroll
        for (int i = 0; i < 8; i++) {
            const float4 x0 = ((const float4*)&sX[(ih * 8 + i) * KI])[0];
            const float4 x1 = ((const float4*)&sX[(ih * 8 + i) * KI])[1];
            float v = wr[2*i].x   * x0.x + wr[2*i].y   * x0.y
                    + wr[2*i].z   * x0.z + wr[2*i].w   * x0.w
                    + wr[2*i+1].x * x1.x + wr[2*i+1].y * x1.y
                    + wr[2*i+1].z * x1.z + wr[2*i+1].w * x1.w;
            up[(size_t)i * (NO * KO)] = __float2half(v);
            acc += v;
        }
        sS[t] = acc;
        __syncthreads();
        if (t < 128) {
            // partial layout: [ich][b][og][k]  (og*KO + k == och*128 + t)
            g_sp[(size_t)(ich * NB + b) * (NO * KO) + och * (K1_OC * KO) + t] =
                sS[t] + sS[t + 128];
        }
    }
}

// ---------------------------------------------------------------------------
// fp16x8 unpack from a uint4
// ---------------------------------------------------------------------------
__device__ __forceinline__ void unpack8(uint4 r, float* f) {
    union { uint4 u; __half2 h[4]; } cv;
    cv.u = r;
#pragma unroll
    for (int q = 0; q < 4; q++) {
        float2 t = __half22float2(cv.h[q]);
        f[2 * q] = t.x;
        f[2 * q + 1] = t.y;
    }
}

// ---------------------------------------------------------------------------
// K2/K3: routing pass. For each (b,i): logits[o] = sum_k vin[b,o,k]*u[b,i,o,k],
// c = softmax over the 64 o (one warp holds all 64: lane l owns o=l and o=l+32),
// accumulate c[o]*u[o,k] into register accumulators, deterministic tree-reduce
// warps -> per-chunk partial in g_sp.
// grid = (18 i-chunks, 64 b), 256 threads (8 warps x 8 i each).
// ---------------------------------------------------------------------------
__global__ void __launch_bounds__(256, 2) k_route(int use_vsum) {
    const float* __restrict__ vin = use_vsum ? g_vsum : g_v1;
    __shared__ float sRed[8 * NO * KO];   // 32 KB: per-warp partials

    const int ich = blockIdx.x;
    const int b = blockIdx.y;
    const int t = threadIdx.x;
    const int w = t >> 5;
    const int l = t & 31;

    // v rows for this lane's two capsules, kept in registers
    float v0[KO], v1[KO];
    {
        const float4* p0 = (const float4*)(vin + ((size_t)b * NO + l) * KO);
        const float4* p1 = (const float4*)(vin + ((size_t)b * NO + l + 32) * KO);
#pragma unroll
        for (int q = 0; q < 4; q++) {
            float4 a = p0[q];
            v0[4*q] = a.x; v0[4*q+1] = a.y; v0[4*q+2] = a.z; v0[4*q+3] = a.w;
            float4 c = p1[q];
            v1[4*q] = c.x; v1[4*q+1] = c.y; v1[4*q+2] = c.z; v1[4*q+3] = c.w;
        }
    }

    float a0[KO], a1[KO];
#pragma unroll
    for (int q = 0; q < KO; q++) { a0[q] = 0.f; a1[q] = 0.f; }

    for (int m = 0; m < K2_IC / 8; m++) {
        const int ig = ich * K2_IC + w * 8 + m;
        const uint4* up = (const uint4*)(g_u + ((size_t)(b * NI + ig)) * (NO * KO));
        uint4 r00 = up[l * 2];
        uint4 r01 = up[l * 2 + 1];
        uint4 r10 = up[(l + 32) * 2];
        uint4 r11 = up[(l + 32) * 2 + 1];
        float u0[KO], u1[KO];
        unpack8(r00, u0); unpack8(r01, u0 + 8);
        unpack8(r10, u1); unpack8(r11, u1 + 8);

        float b0 = 0.f, b1 = 0.f;
#pragma unroll
        for (int q = 0; q < KO; q++) { b0 += v0[q] * u0[q]; b1 += v1[q] * u1[q]; }

        // exact softmax over all 64 o within the warp
        float mx = fmaxf(b0, b1);
#pragma unroll
        for (int d = 16; d > 0; d >>= 1)
            mx = fmaxf(mx, __shfl_xor_sync(0xffffffffu, mx, d));
        float e0 = __expf(b0 - mx);
        float e1 = __expf(b1 - mx);
        float sm = e0 + e1;
#pragma unroll
        for (int d = 16; d > 0; d >>= 1)
            sm += __shfl_xor_sync(0xffffffffu, sm, d);
        float inv = __fdividef(1.f, sm);
        float c0 = e0 * inv, c1 = e1 * inv;
#pragma unroll
        for (int q = 0; q < KO; q++) { a0[q] += c0 * u0[q]; a1[q] += c1 * u1[q]; }
    }

    // deterministic reduction of the 8 warp accumulators
    float4* sr4 = (float4*)sRed;
#pragma unroll
    for (int q = 0; q < 4; q++) {
        sr4[(w * NO + l) * 4 + q]        = make_float4(a0[4*q], a0[4*q+1], a0[4*q+2], a0[4*q+3]);
        sr4[(w * NO + l + 32) * 4 + q]   = make_float4(a1[4*q], a1[4*q+1], a1[4*q+2], a1[4*q+3]);
    }
    __syncthreads();
    float4 r = sr4[t];
#pragma unroll
    for (int ww = 1; ww < 8; ww++) {
        float4 p = sr4[ww * 256 + t];
        r.x += p.x; r.y += p.y; r.z += p.z; r.w += p.w;
    }
    ((float4*)(g_sp + (size_t)(ich * NB + b) * (NO * KO)))[t] = r;
}

// ---------------------------------------------------------------------------
// Reduce chunk partials -> s[b,o,:], squash, write v.
// mode 0: v1 = squash(s/64);  mode 1: vsum = v1 + squash(s);  mode 2: out = squash(s)
// 4096 threads, one per (b,o).
// ---------------------------------------------------------------------------
__global__ void __launch_bounds__(256) k_reduce(int nch, float scale, int mode,
                                                float* __restrict__ dout) {
    const int tg = blockIdx.x * 256 + threadIdx.x;   // 0..4095 == b*NO + o
    const size_t boff = (size_t)tg * KO;
    float s[KO];
#pragma unroll
    for (int q = 0; q < KO; q++) s[q] = 0.f;
    const float* base = g_sp + boff;
#pragma unroll 2
    for (int c = 0; c < nch; c++) {
        const float4* p = (const float4*)(base + (size_t)c * (NB * NO * KO));
#pragma unroll
        for (int q = 0; q < 4; q++) {
            float4 a = p[q];
            s[4*q] += a.x; s[4*q+1] += a.y; s[4*q+2] += a.z; s[4*q+3] += a.w;
        }
    }
    float n2 = 0.f;
#pragma unroll
    for (int q = 0; q < KO; q++) { s[q] *= scale; n2 += s[q] * s[q]; }
    const float scl = n2 / (1.f + n2) * rsqrtf(n2 + 1e-7f);

    if (mode == 0) {
#pragma unroll
        for (int q = 0; q < KO; q++) g_v1[boff + q] = s[q] * scl;
    } else if (mode == 1) {
#pragma unroll
        for (int q = 0; q < KO; q++) g_vsum[boff + q] = s[q] * scl + g_v1[boff + q];
    } else {
#pragma unroll
        for (int q = 0; q < KO; q++) dout[boff + q] = s[q] * scl;
    }
}

// ---------------------------------------------------------------------------
extern "C" void kernel_launch(void* const* d_in, const int* in_sizes, int n_in,
                              void* d_out, int out_size) {
    const float* x = (const float*)d_in[0];
    const float* W = (const float*)d_in[1];
    if (in_sizes[0] != NB * NI * KI) {   // defensive input-order check
        x = (const float*)d_in[1];
        W = (const float*)d_in[0];
    }
    float* out = (float*)d_out;

    k_u<<<dim3(NCH1, NO / K1_OC), 256>>>(x, W);                 // u + s1 partials
    k_reduce<<<16, 256>>>(NCH1, 1.f / 64.f, 0, nullptr);        // v1
    k_route<<<dim3(NCH2, NB), 256>>>(0);                        // s2 partials (b1 = v1.u)
    k_reduce<<<16, 256>>>(NCH2, 1.f, 1, nullptr);               // v2, vsum = v1+v2
    k_route<<<dim3(NCH2, NB), 256>>>(1);                        // s3 partials (b2 = vsum.u)
    k_reduce<<<16, 256>>>(NCH2, 1.f, 2, out);                   // v3 -> out
}

// round 3
// speedup vs baseline: 1.5285x; 1.5285x over previous
#include <cuda_runtime.h>
#include <cuda_fp16.h>
#include <cstdint>

// Routed capsule layer, B200 (sm_100a).
// x[64,1152,8], W[64,1152,16,8] -> v[64,64,16], 3 routing iterations.
// b_t = (sum_{tau<=t} v_tau) . u  (logits linear in history); iter-1 c == 1/64.
// u cached in fp16, layout [b][i][o][k].

#define NB 64
#define NI 1152
#define KI 8
#define NO 64
#define KO 16

#define K1_IC 16
#define NCH1 (NI / K1_IC)   // 72 i-chunks for k_u partials
#define K2_IC 64
#define NCH2 (NI / K2_IC)   // 18 i-chunks for k_route partials

__device__ __half g_u[(size_t)NB * NI * NO * KO];    // 151 MB
__device__ float g_sp[(size_t)NCH1 * NB * NO * KO];  // partial s buffers
__device__ float g_v1[NB * NO * KO];
__device__ float g_vsum[NB * NO * KO];

// ---------------------------------------------------------------------------
// K1: u = W.x (fp16) + per-chunk partial sums (uniform-c first iteration).
// Block: 256 threads = 8 warps (one o each); lane = ih*16 + k; thread owns
// W[og][16 ich + ih*8 + i][k][:] in registers (read from DRAM exactly once).
// Whole x tile (all 64 b) staged in smem once -> NO barriers in the b loop.
// grid = (72 i-chunks, 8 o-chunks).
// ---------------------------------------------------------------------------
__global__ void __launch_bounds__(256, 2) k_u(const float* __restrict__ x,
                                              const float* __restrict__ W) {
    __shared__ float sX[NB * K1_IC * KI];   // 32 KB: [b][i_local][j]

    const int ich = blockIdx.x, och = blockIdx.y;
    const int t = threadIdx.x;
    const int w = t >> 5;                   // local o
    const int l = t & 31;
    const int ih = l >> 4, k = l & 15;
    const int og = och * 8 + w;

    // stage x for ALL batches: 2048 float4, 8 per thread
    {
        const float4* xs = (const float4*)(x + (size_t)ich * K1_IC * KI);
        float4* sx4 = (float4*)sX;
#pragma unroll
        for (int it = 0; it < 8; it++) {
            int idx = t + it * 256;          // 0..2047
            int b = idx >> 5, r = idx & 31;
            sx4[idx] = xs[(size_t)b * (NI * KI / 4) + r];
        }
    }

    // register-resident W slice: 8 i x 8 j
    float4 wr[16];
    {
        const float4* wp = (const float4*)(
            W + ((size_t)(og * NI + ich * K1_IC + ih * 8) * KO + k) * KI);
#pragma unroll
        for (int i = 0; i < 8; i++) {
            wr[2 * i]     = wp[i * 32];
            wr[2 * i + 1] = wp[i * 32 + 1];
        }
    }
    __syncthreads();

    for (int b = 0; b < NB; b++) {
        float acc = 0.f;
        __half* up = g_u + ((size_t)(b * NI + ich * K1_IC + ih * 8)) * (NO * KO)
                   + og * KO + k;
        const float4* xb = (const float4*)(sX + b * (K1_IC * KI) + ih * 64);
#pragma unroll
        for (int i = 0; i < 8; i++) {
            const float4 x0 = xb[2 * i];
            const float4 x1 = xb[2 * i + 1];
            float v = wr[2*i].x   * x0.x + wr[2*i].y   * x0.y
                    + wr[2*i].z   * x0.z + wr[2*i].w   * x0.w
                    + wr[2*i+1].x * x1.x + wr[2*i+1].y * x1.y
                    + wr[2*i+1].z * x1.z + wr[2*i+1].w * x1.w;
            up[(size_t)i * (NO * KO)] = __float2half(v);
            acc += v;
        }
        acc += __shfl_xor_sync(0xffffffffu, acc, 16);   // join the two i-halves
        if (l < 16)
            g_sp[(size_t)(ich * NB + b) * (NO * KO) + og * KO + l] = acc;
    }
}

// fp16x8 unpack from a uint4
__device__ __forceinline__ void unpack8(uint4 r, float* f) {
    union { uint4 u; __half2 h[4]; } cv;
    cv.u = r;
#pragma unroll
    for (int q = 0; q < 4; q++) {
        float2 t = __half22float2(cv.h[q]);
        f[2 * q] = t.x;
        f[2 * q + 1] = t.y;
    }
}

// ---------------------------------------------------------------------------
// K2/K3: routing pass. Warp handles one (b,i) at a time: lane l owns the
// kh=(l&1) half (8 k's) of o in {l>>1, 16+(l>>1), 32+(l>>1), 48+(l>>1)} so the
// four uint4 u loads are perfectly coalesced (up[l], up[l+32], up[l+64],
// up[l+96] = 4 contiguous 512B warp transactions). Logit = partial + partner
// (shfl_xor 1); softmax reduction over xor {2,4,8,16} touches each o once.
// grid = (18 i-chunks, 64 b), 256 threads (8 warps x 8 i each).
// ---------------------------------------------------------------------------
__global__ void __launch_bounds__(256, 2) k_route(int use_vsum) {
    const float* __restrict__ vin = use_vsum ? g_vsum : g_v1;
    __shared__ float sRed[8 * NO * KO];     // 32 KB per-warp partials

    const int ich = blockIdx.x, b = blockIdx.y;
    const int t = threadIdx.x, w = t >> 5, l = t & 31;
    const int o0 = l >> 1, kh = l & 1;

    // v slices for this lane's 4 capsules (8 floats each)
    float v[4][8];
#pragma unroll
    for (int m = 0; m < 4; m++) {
        const float4* p = (const float4*)(vin + ((size_t)b * NO + (m * 16 + o0)) * KO + kh * 8);
        float4 a = p[0], c = p[1];
        v[m][0]=a.x; v[m][1]=a.y; v[m][2]=a.z; v[m][3]=a.w;
        v[m][4]=c.x; v[m][5]=c.y; v[m][6]=c.z; v[m][7]=c.w;
    }
    float acc[4][8];
#pragma unroll
    for (int m = 0; m < 4; m++)
#pragma unroll
        for (int q = 0; q < 8; q++) acc[m][q] = 0.f;

    for (int it = 0; it < 8; it++) {
        const int ig = ich * K2_IC + w * 8 + it;
        const uint4* up = (const uint4*)(g_u + (size_t)(b * NI + ig) * (NO * KO));
        uint4 R0 = up[l];
        uint4 R1 = up[l + 32];
        uint4 R2 = up[l + 64];
        uint4 R3 = up[l + 96];
        float u[4][8];
        unpack8(R0, u[0]); unpack8(R1, u[1]); unpack8(R2, u[2]); unpack8(R3, u[3]);

        float L[4];
#pragma unroll
        for (int m = 0; m < 4; m++) {
            float p = 0.f;
#pragma unroll
            for (int q = 0; q < 8; q++) p += v[m][q] * u[m][q];
            L[m] = p + __shfl_xor_sync(0xffffffffu, p, 1);   // full 16-k dot
        }
        float mx = fmaxf(fmaxf(L[0], L[1]), fmaxf(L[2], L[3]));
#pragma unroll
        for (int d = 2; d <= 16; d <<= 1)
            mx = fmaxf(mx, __shfl_xor_sync(0xffffffffu, mx, d));
        float e[4];
        float sm = 0.f;
#pragma unroll
        for (int m = 0; m < 4; m++) { e[m] = __expf(L[m] - mx); sm += e[m]; }
#pragma unroll
        for (int d = 2; d <= 16; d <<= 1)
            sm += __shfl_xor_sync(0xffffffffu, sm, d);
        const float inv = __fdividef(1.f, sm);
#pragma unroll
        for (int m = 0; m < 4; m++) {
            const float c = e[m] * inv;
#pragma unroll
            for (int q = 0; q < 8; q++) acc[m][q] += c * u[m][q];
        }
    }

    // per-warp partials -> smem; element index for (m,lane) is 256*m + 8*l + q
    float4* sr4 = (float4*)sRed;
#pragma unroll
    for (int m = 0; m < 4; m++) {
        sr4[w * 256 + m * 64 + 2 * l]     = make_float4(acc[m][0], acc[m][1], acc[m][2], acc[m][3]);
        sr4[w * 256 + m * 64 + 2 * l + 1] = make_float4(acc[m][4], acc[m][5], acc[m][6], acc[m][7]);
    }
    __syncthreads();
    float4 r = sr4[t];
#pragma unroll
    for (int ww = 1; ww < 8; ww++) {
        float4 p = sr4[ww * 256 + t];
        r.x += p.x; r.y += p.y; r.z += p.z; r.w += p.w;
    }
    ((float4*)(g_sp + (size_t)(ich * NB + b) * (NO * KO)))[t] = r;
}

// ---------------------------------------------------------------------------
// Reduce chunk partials -> s, squash, write v. One thread per (b,o,k) element
// (65536 threads); norm over the 16 k's via shfl within 16-lane groups.
// mode 0: v1 = squash(s/64); mode 1: vsum = v1 + squash(s); mode 2: out.
// ---------------------------------------------------------------------------
__global__ void __launch_bounds__(256) k_reduce(int nch, float scale, int mode,
                                                float* __restrict__ dout) {
    const int tg = blockIdx.x * 256 + threadIdx.x;   // b*1024 + o*16 + k
    float s = 0.f;
    const float* p = g_sp + tg;
#pragma unroll 4
    for (int c = 0; c < nch; c++) s += p[(size_t)c * (NB * NO * KO)];
    s *= scale;
    float n2 = s * s;
#pragma unroll
    for (int d = 1; d <= 8; d <<= 1)
        n2 += __shfl_xor_sync(0xffffffffu, n2, d);   // stays within k-group
    const float scl = n2 / (1.f + n2) * rsqrtf(n2 + 1e-7f);
    const float val = s * scl;
    if (mode == 0)      g_v1[tg] = val;
    else if (mode == 1) g_vsum[tg] = val + g_v1[tg];
    else                dout[tg] = val;
}

// ---------------------------------------------------------------------------
extern "C" void kernel_launch(void* const* d_in, const int* in_sizes, int n_in,
                              void* d_out, int out_size) {
    const float* x = (const float*)d_in[0];
    const float* W = (const float*)d_in[1];
    if (in_sizes[0] != NB * NI * KI) {
        x = (const float*)d_in[1];
        W = (const float*)d_in[0];
    }
    float* out = (float*)d_out;

    k_u<<<dim3(NCH1, NO / 8), 256>>>(x, W);          // u + s1 partials
    k_reduce<<<256, 256>>>(NCH1, 1.f / 64.f, 0, nullptr);   // v1
    k_route<<<dim3(NCH2, NB), 256>>>(0);             // s2 partials (b1 = v1.u)
    k_reduce<<<256, 256>>>(NCH2, 1.f, 1, nullptr);   // v2, vsum = v1+v2
    k_route<<<dim3(NCH2, NB), 256>>>(1);             // s3 partials (b2 = vsum.u)
    k_reduce<<<256, 256>>>(NCH2, 1.f, 2, out);       // v3 -> out
}